// round 11
// baseline (speedup 1.0000x reference)
#include <cuda_runtime.h>
#include <cuda_fp16.h>
#include <math.h>
#include <stdint.h>

#define N 768
#define NT 50
#define NN (N*N)
#define SIGMA 0.1f
#define RES 100
#define NL 5
#define S_ITERS 11      // s <= 12 -> q <= 11 -> active iters i < q <= 11, i.e. i <= 10
#define KC 32
#define NCHUNK (N/KC)   // 24

// Taylor coefficients 1/k!
#define C0  1.0f
#define C1  1.0f
#define C2  0.5f
#define C3  (1.0f/6.0f)
#define C4  (1.0f/24.0f)
#define C5  (1.0f/120.0f)
#define C6  (1.0f/720.0f)
#define C7  (1.0f/5040.0f)
#define C8  (1.0f/40320.0f)
#define C9  (1.0f/362880.0f)
#define C10 (1.0f/3628800.0f)
#define C11 (1.0f/39916800.0f)
#define C12 (2.0876757e-9f)
#define C13 (1.6059044e-10f)
#define C14 (1.1470746e-11f)
#define C15 (7.6471637e-13f)

// epilogue write modes
#define WM_NEVER  0
#define WM_ALWAYS 1
#define WM_LAST   2   // iff iter == q-1
#define WM_Q0     3   // iff q == 0
#define WM_NOTLAST 4  // iff iter < q-1

// ---------------- global scratch ----------------
__device__ float g_dist[NN];
__device__ float g_r[NT*N];
__device__ float g_rmax[NT];
__device__ int   g_s[NT];
__device__ int   g_q[NT];
__device__ float g_scale[NT];
__device__ float g_maxdist;
__device__ float g_betti[NT];
// fp32 buffers: 0=M 1=M2 2=M3 3=M4 4/5 = ping-pong
// NOTE: g_buf[5] doubles as the unscaled-sigmoid cache between rowsum and
// buildM; it is first written as a GEMM output at the "B5 = M4*B4 + G2"
// stage (limbs) and its fp32 plane only at final-exp (q==0) / last squaring,
// both strictly after buildM has consumed the adjacency. No overlap.
__device__ float g_buf[6][(size_t)NT*NN];
// fp16 limb planes (2 per buffer); 16B-aligned for cp.async/uint2
__device__ __align__(16) __half g_limb[6][2][(size_t)NT*NN];

// ---------------- helpers ----------------
__device__ __forceinline__ void atomicMaxF(float* addr, float v) {
    atomicMax((int*)addr, __float_as_int(v));   // non-negative floats
}
__device__ __forceinline__ uint32_t smem_u32(const void* p) {
    uint32_t a;
    asm("{ .reg .u64 t; cvta.to.shared.u64 t, %1; cvt.u32.u64 %0, t; }" : "=r"(a) : "l"(p));
    return a;
}
__device__ __forceinline__ void cp16(uint32_t s, const void* g) {
    asm volatile("cp.async.cg.shared.global [%0], [%1], 16;" :: "r"(s), "l"(g));
}
#define CP_COMMIT() asm volatile("cp.async.commit_group;" ::: "memory")
#define CP_WAIT(n)  asm volatile("cp.async.wait_group %0;" :: "n"(n) : "memory")

__device__ __forceinline__ void ldm_x4(uint32_t* r, uint32_t addr) {
    asm volatile("ldmatrix.sync.aligned.m8n8.x4.shared.b16 {%0,%1,%2,%3}, [%4];"
                 : "=r"(r[0]), "=r"(r[1]), "=r"(r[2]), "=r"(r[3]) : "r"(addr));
}
__device__ __forceinline__ void mma16816(float* d, const uint32_t* a, const uint32_t* b) {
    asm volatile(
        "mma.sync.aligned.m16n8k16.row.col.f32.f16.f16.f32 "
        "{%0,%1,%2,%3}, {%4,%5,%6,%7}, {%8,%9}, {%0,%1,%2,%3};"
        : "+f"(d[0]), "+f"(d[1]), "+f"(d[2]), "+f"(d[3])
        : "r"(a[0]), "r"(a[1]), "r"(a[2]), "r"(a[3]), "r"(b[0]), "r"(b[1]));
}

__device__ __forceinline__ uint32_t packh(__half lo, __half hi) {
    __half2 t = __halves2half2(lo, hi);
    return *reinterpret_cast<uint32_t*>(&t);
}
__device__ __forceinline__ void split2(float x, __half& h0, __half& h1) {
    h0 = __float2half_rn(x);
    h1 = __float2half_rn(x - __half2float(h0));
}
__device__ __forceinline__ void split2x4(float4 v, uint2& L0, uint2& L1) {
    __half a0,a1,b0,b1,c0,c1,d0,d1;
    split2(v.x, a0,a1); split2(v.y, b0,b1);
    split2(v.z, c0,c1); split2(v.w, d0,d1);
    L0 = make_uint2(packh(a0,b0), packh(c0,d0));
    L1 = make_uint2(packh(a1,b1), packh(c1,d1));
}

// ---------------- small kernels ----------------
__global__ void init_kernel() {
    int t = threadIdx.x;
    if (t < NT) g_rmax[t] = 0.0f;
    if (t == 0) g_maxdist = 0.0f;
}

__global__ void dist_kernel(const float* __restrict__ pts) {
    __shared__ float p[N*3];
    for (int i = threadIdx.x; i < N*3; i += blockDim.x) p[i] = pts[i];
    __syncthreads();
    int idx = blockIdx.x * blockDim.x + threadIdx.x;
    float d = 0.0f;
    if (idx < NN) {
        int i = idx / N, j = idx - i*N;
        float dx = p[i*3+0] - p[j*3+0];
        float dy = p[i*3+1] - p[j*3+1];
        float dz = p[i*3+2] - p[j*3+2];
        d = sqrtf(dx*dx + dy*dy + dz*dz);
        g_dist[idx] = d;
    }
    __shared__ float red[256];
    red[threadIdx.x] = d;
    __syncthreads();
    for (int off = 128; off > 0; off >>= 1) {
        if (threadIdx.x < off) red[threadIdx.x] = fmaxf(red[threadIdx.x], red[threadIdx.x+off]);
        __syncthreads();
    }
    if (threadIdx.x == 0) atomicMaxF(&g_maxdist, red[0]);
}

// one block per (t, i): computes sigmoid row ONCE, caches it (unscaled) in
// g_buf[5], and reduces the off-diagonal row sum. Eliminates the duplicate
// 29.5M-expf pass in buildM (~200 us of MUFU).
__global__ void adj_rowsum_kernel() {
    int bid = blockIdx.x;           // t*N + i
    int t = bid / N, i = bid - t*N;
    float th = ((float)t / (float)(NT-1)) * g_maxdist;
    const float* drow = g_dist + (size_t)i*N;
    float* arow = g_buf[5] + (size_t)t*NN + (size_t)i*N;
    float s = 0.0f;
    for (int j = threadIdx.x; j < N; j += blockDim.x) {
        float e = expf((drow[j] - th) / SIGMA);
        float a = 1.0f / (1.0f + e);
        arow[j] = a;
        if (j != i) s += a;
    }
    __shared__ float red[128];
    red[threadIdx.x] = s;
    __syncthreads();
    for (int off = 64; off > 0; off >>= 1) {
        if (threadIdx.x < off) red[threadIdx.x] += red[threadIdx.x+off];
        __syncthreads();
    }
    if (threadIdx.x == 0) {
        g_r[bid] = red[0];
        atomicMaxF(&g_rmax[t], red[0]);
    }
}

// Gershgorin bound: lambda_max(L) <= 2*max_row_sum. The slack in this bound
// is load-bearing: it keeps true ||M|| ~ theta/2, which the fp16-limb PS
// chain needs (round-8's tight bound pushed true ||M|| to ~4 and blew up
// high-order-term quantization error to 5e-3).
__global__ void sq_kernel() {
    int t = threadIdx.x;
    if (t < NT) {
        float x = 2.0f * g_rmax[t] / SIGMA;
        int s = 0;
        if (x > 4.0f) s = (int)ceilf(log2f(x * 0.25f));   // scale to ||M|| <= 4
        if (s < 0) s = 0;
        if (s > 12) s = 12;
        g_s[t] = s;
        g_q[t] = (s > 1) ? (s - 1) : 0;
        g_scale[t] = exp2f((float)(-s)) / SIGMA;
    }
}

// M = -L/(sigma*2^s) from the cached adjacency; also emit fp16 limbs of M
__global__ void buildM_kernel() {
    int t = blockIdx.y;
    int idx = blockIdx.x * blockDim.x + threadIdx.x;
    if (idx >= NN) return;
    int i = idx / N, j = idx - i*N;
    float sc = g_scale[t];
    size_t o = (size_t)t*NN + idx;
    float v = (i == j) ? (-g_r[t*N + i] * sc) : (g_buf[5][o] * sc);
    g_buf[0][o] = v;
    __half h0, h1;
    split2(v, h0, h1);
    g_limb[0][0][o] = h0; g_limb[0][1][o] = h1;
}

// buf4 = C12*I + C13*M + C14*M2 + C15*M3 (limbs only; buf4 is a GEMM operand)
__global__ void elw_g3_kernel() {
    int t = blockIdx.y;
    int idx = blockIdx.x * blockDim.x + threadIdx.x;
    if (idx >= NN) return;
    int i = idx / N, j = idx - i*N;
    size_t o = (size_t)t*NN + idx;
    float v = C13*g_buf[0][o] + C14*g_buf[1][o] + C15*g_buf[2][o];
    if (i == j) v += C12;
    __half h0, h1;
    split2(v, h0, h1);
    g_limb[4][0][o] = h0; g_limb[4][1][o] = h1;
}

// ---------------- mma.sync batched GEMM (fp16 2-limb, 3 products) ----------------
// smem: 2 buffers x 4 limb tiles (A0 A1 B0 B1); tile = 128 rows x 32 fp16, pitch 80B
#define TILEB 10240          // 128*80
#define BUFB  (4*TILEB)      // 40960
#define SMEMB (2*BUFB)       // 81920
#define CPIT  132            // C_sm pitch (floats); multiple of 4 -> 16B rows

__global__ void __launch_bounds__(256, 2) gemm_mma(int ai, int bi, int ci, int addG,
                                                   float gc0, float gc1, float gc2, float gc3,
                                                   int iter, int fmode, int lmode)
{
    int t = blockIdx.z;
    int q = g_q[t];
    if (iter >= 0 && iter >= q) return;

    bool wF = (fmode == WM_ALWAYS) || (fmode == WM_LAST && iter == q-1) || (fmode == WM_Q0 && q == 0);
    bool wL = (lmode == WM_ALWAYS) || (lmode == WM_NOTLAST && iter < q-1);

    // lower-triangular tile decode (21 tiles of 6x6)
    int r = 0, rem = blockIdx.x;
    while (rem > r) { rem -= (r + 1); r++; }
    int btr = r, btc = rem;            // tile row >= tile col
    int row0 = btr * 128, col0 = btc * 128;

    extern __shared__ char smem[];
    uint32_t sb = smem_u32(smem);
    int tid = threadIdx.x;
    int wid = tid >> 5, lane = tid & 31;
    int wm = wid >> 2, wn = wid & 3;   // warp tile: rows wm*64, cols wn*32

    bool same = (ai == bi) && (btr == btc);
    const __half* pA[2] = { g_limb[ai][0] + (size_t)t*NN, g_limb[ai][1] + (size_t)t*NN };
    const __half* pB[2] = { g_limb[bi][0] + (size_t)t*NN, g_limb[bi][1] + (size_t)t*NN };
    float* C = g_buf[ci] + (size_t)t*NN;

    float acc[4][4][4];
    #pragma unroll
    for (int a = 0; a < 4; a++)
        #pragma unroll
        for (int b = 0; b < 4; b++)
            #pragma unroll
            for (int c = 0; c < 4; c++) acc[a][b][c] = 0.0f;

    // lane-invariant ldmatrix offsets
    uint32_t aLane = (uint32_t)((wm*64 + (lane & 15))*80 + ((lane >> 4)*16));
    uint32_t bLane = (uint32_t)((wn*32 + (lane & 7) + ((lane >> 4) << 3))*80 + (((lane >> 3) & 1)*16));
    const int nTiles = same ? 2 : 4;
    const int totCp = nTiles * 512;

    // ---- async-copy producer ----
    auto issue = [&](int c, int buf) {
        uint32_t bb = sb + buf*BUFB;
        int cK = c*KC;
        for (int idx = tid; idx < totCp; idx += 256) {
            int tile = idx >> 9;
            int rr2 = (idx & 511) >> 2, q2 = idx & 3;
            const __half* src = (tile < 2)
                ? pA[tile] + (size_t)(row0 + rr2)*N + cK + q2*8
                : pB[tile-2] + (size_t)(col0 + rr2)*N + cK + q2*8;
            cp16(bb + tile*TILEB + rr2*80 + q2*16, src);
        }
    };

    issue(0, 0); CP_COMMIT();

    for (int c = 0; c < NCHUNK; c++) {
        if (c + 1 < NCHUNK) { issue(c+1, (c+1)&1); CP_COMMIT(); CP_WAIT(1); }
        else CP_WAIT(0);
        __syncthreads();

        uint32_t bb  = sb + (c&1)*BUFB;
        uint32_t bbB = same ? bb : bb + 2*TILEB;
        #pragma unroll
        for (int ks = 0; ks < 2; ks++) {
            uint32_t af0[4][4], af1[4][4], bf0[2][4], bf1[2][4];
            {
                uint32_t base = bbB + bLane + ks*32;
                ldm_x4(bf0[0], base);            ldm_x4(bf0[1], base + 16*80);
                ldm_x4(bf1[0], base + TILEB);    ldm_x4(bf1[1], base + TILEB + 16*80);
            }
            {
                uint32_t base = bb + aLane + ks*32;
                #pragma unroll
                for (int mt = 0; mt < 4; mt++) {
                    ldm_x4(af0[mt], base + mt*16*80);
                    ldm_x4(af1[mt], base + TILEB + mt*16*80);
                }
            }
            // 3 limb products, PRODUCT-FIRST order: 16 independent accumulators
            // between reuses (the old per-(mt,nt) x3 order formed RAW chains
            // through each accumulator).
            #pragma unroll
            for (int mt = 0; mt < 4; mt++)
                #pragma unroll
                for (int nt = 0; nt < 4; nt++)
                    mma16816(acc[mt][nt], af0[mt], &bf0[nt>>1][(nt&1)*2]);
            #pragma unroll
            for (int mt = 0; mt < 4; mt++)
                #pragma unroll
                for (int nt = 0; nt < 4; nt++)
                    mma16816(acc[mt][nt], af0[mt], &bf1[nt>>1][(nt&1)*2]);
            #pragma unroll
            for (int mt = 0; mt < 4; mt++)
                #pragma unroll
                for (int nt = 0; nt < 4; nt++)
                    mma16816(acc[mt][nt], af1[mt], &bf0[nt>>1][(nt&1)*2]);
        }
        __syncthreads();
    }

    // ---- epilogue via smem (coalesced stores + mirror + limb emission) ----
    float* C_sm = (float*)smem;
    {
        int g = lane >> 2, j2 = (lane & 3) * 2;
        #pragma unroll
        for (int mt = 0; mt < 4; mt++)
            #pragma unroll
            for (int nt = 0; nt < 4; nt++) {
                int rr = wm*64 + mt*16 + g;
                int cc = wn*32 + nt*8 + j2;
                C_sm[rr*CPIT + cc]       = acc[mt][nt][0];
                C_sm[rr*CPIT + cc + 1]   = acc[mt][nt][1];
                C_sm[(rr+8)*CPIT + cc]   = acc[mt][nt][2];
                C_sm[(rr+8)*CPIT + cc+1] = acc[mt][nt][3];
            }
    }
    __syncthreads();

    const float* Mp  = g_buf[0] + (size_t)t*NN;
    const float* M2p = g_buf[1] + (size_t)t*NN;
    const float* M3p = g_buf[2] + (size_t)t*NN;
    __half* L0 = g_limb[ci][0] + (size_t)t*NN;
    __half* L1 = g_limb[ci][1] + (size_t)t*NN;

    {   // phase A: lower tile, row-coalesced
        int rr = tid & 127, h = tid >> 7;
        size_t rowOff = (size_t)(row0 + rr)*N + col0;
        #pragma unroll
        for (int i = 0; i < 16; i++) {
            int ce = h*64 + i*4;
            float4 v = *(float4*)&C_sm[rr*CPIT + ce];
            if (addG) {
                float4 m1 = *(const float4*)(Mp  + rowOff + ce);
                float4 m2 = *(const float4*)(M2p + rowOff + ce);
                float4 m3 = *(const float4*)(M3p + rowOff + ce);
                v.x += gc1*m1.x + gc2*m2.x + gc3*m3.x;
                v.y += gc1*m1.y + gc2*m2.y + gc3*m3.y;
                v.z += gc1*m1.z + gc2*m2.z + gc3*m3.z;
                v.w += gc1*m1.w + gc2*m2.w + gc3*m3.w;
                if (btr == btc) {
                    int k = rr - ce;
                    if (k >= 0 && k < 4) (&v.x)[k] += gc0;
                }
                if (btr != btc) *(float4*)&C_sm[rr*CPIT + ce] = v;  // mirror reads adjusted
            }
            if (wF) *(float4*)(C + rowOff + ce) = v;
            if (wL) {
                uint2 l0, l1;
                split2x4(v, l0, l1);
                *(uint2*)(L0 + rowOff + ce) = l0;
                *(uint2*)(L1 + rowOff + ce) = l1;
            }
        }
    }
    if (btr != btc) {   // phase B: mirror (transpose out of smem)
        __syncthreads();
        int u = tid >> 1, hh = tid & 1;
        size_t rowOff = (size_t)(col0 + u)*N + row0;
        #pragma unroll
        for (int i = 0; i < 16; i++) {
            int x0 = hh*64 + i*4;
            float4 v = make_float4(C_sm[(x0  )*CPIT + u], C_sm[(x0+1)*CPIT + u],
                                   C_sm[(x0+2)*CPIT + u], C_sm[(x0+3)*CPIT + u]);
            if (wF) *(float4*)(C + rowOff + x0) = v;
            if (wL) {
                uint2 l0, l1;
                split2x4(v, l0, l1);
                *(uint2*)(L0 + rowOff + x0) = l0;
                *(uint2*)(L1 + rowOff + x0) = l1;
            }
        }
    }
}

// betti[t] = s==0 ? tr(X) : ||X||_F^2   with X in buffer 5 (q even) or 4 (q odd)
__global__ void frob_kernel() {
    int t = blockIdx.x;
    int s = g_s[t], q = g_q[t];
    const float* X = g_buf[(q & 1) ? 4 : 5] + (size_t)t*NN;
    double acc = 0.0;
    if (s == 0) {
        for (int i = threadIdx.x; i < N; i += blockDim.x)
            acc += (double)X[(size_t)i*N + i];
    } else {
        for (int idx = threadIdx.x; idx < NN; idx += blockDim.x) {
            double v = X[idx];
            acc += v * v;
        }
    }
    __shared__ double red[256];
    red[threadIdx.x] = acc;
    __syncthreads();
    for (int off = 128; off > 0; off >>= 1) {
        if (threadIdx.x < off) red[threadIdx.x] += red[threadIdx.x+off];
        __syncthreads();
    }
    if (threadIdx.x == 0) g_betti[t] = (float)red[0];
}

__global__ void final_kernel(float* __restrict__ out) {
    __shared__ float b[NT];
    __shared__ float bi[RES], sm[RES], dv[RES];
    __shared__ float red;
    int tid = threadIdx.x;
    if (tid < NT) b[tid] = g_betti[tid];
    __syncthreads();
    if (tid < RES) {
        float pos = (float)(NT-1) * (float)tid / (float)(RES-1);
        int i0 = (int)floorf(pos);
        if (i0 > NT-2) i0 = NT-2;
        if (i0 < 0) i0 = 0;
        float fr = pos - (float)i0;
        bi[tid] = b[i0]*(1.0f - fr) + b[i0+1]*fr;
    }
    __syncthreads();
    if (tid == 0) {
        float m = bi[0];
        for (int i = 1; i < RES; i++) m = fmaxf(m, bi[i]);
        red = m;
    }
    __syncthreads();
    if (tid < RES) out[tid] = bi[tid] / (red + 1e-8f);

    for (int k = 1; k < NL; k++) {
        int ks = 2*k + 1;
        int pad = ks / 2;
        __syncthreads();
        if (tid < RES) {
            float s = 0.0f;
            for (int u = -pad; u <= pad; u++) {
                int j = tid + u;
                j = max(0, min(RES-1, j));
                s += bi[j];
            }
            sm[tid] = s / (float)ks;
        }
        __syncthreads();
        if (tid < RES) {
            float d = (tid < RES-1) ? (sm[tid+1] - sm[tid]) : (sm[RES-1] - sm[RES-2]);
            dv[tid] = d;
        }
        __syncthreads();
        if (tid == 0) {
            float m = fabsf(dv[0]);
            for (int i = 1; i < RES; i++) m = fmaxf(m, fabsf(dv[i]));
            red = m;
        }
        __syncthreads();
        if (tid < RES) out[k*RES + tid] = dv[tid] / (red + 1e-8f);
    }
}

extern "C" void kernel_launch(void* const* d_in, const int* in_sizes, int n_in,
                              void* d_out, int out_size)
{
    const float* pts = (const float*)d_in[0];
    float* out = (float*)d_out;

    cudaFuncSetAttribute(gemm_mma, cudaFuncAttributeMaxDynamicSharedMemorySize, SMEMB);

    init_kernel<<<1, 64>>>();
    dist_kernel<<<NN/256, 256>>>(pts);
    adj_rowsum_kernel<<<NT*N, 128>>>();     // sigmoids computed ONCE -> g_buf[5]
    sq_kernel<<<1, 64>>>();

    dim3 gE(NN/256, NT);
    buildM_kernel<<<gE, 256>>>();           // reads cached adjacency

    dim3 gG(21, 1, NT);
    // Taylor degree 15, Paterson-Stockmeyer q=4
    // M2: fp32 (elw_g3 + addG read it) + limbs
    gemm_mma<<<gG, 256, SMEMB>>>(0, 0, 1, 0, 0,0,0,0, -1, WM_ALWAYS, WM_ALWAYS);
    // M3: fp32 only (elw_g3 + addG read it); never a GEMM operand
    gemm_mma<<<gG, 256, SMEMB>>>(1, 0, 2, 0, 0,0,0,0, -1, WM_ALWAYS, WM_NEVER);
    // M4: limbs only (pure GEMM operand)
    gemm_mma<<<gG, 256, SMEMB>>>(1, 1, 3, 0, 0,0,0,0, -1, WM_NEVER, WM_ALWAYS);
    elw_g3_kernel<<<gE, 256>>>();   // B4 limbs = G3
    // PS intermediates: limbs only
    gemm_mma<<<gG, 256, SMEMB>>>(3, 4, 5, 1, C8, C9, C10, C11, -1, WM_NEVER, WM_ALWAYS);
    gemm_mma<<<gG, 256, SMEMB>>>(3, 5, 4, 1, C4, C5, C6,  C7,  -1, WM_NEVER, WM_ALWAYS);
    // exp(M): limbs always (squaring operand); fp32 only where q==0 (frob input)
    gemm_mma<<<gG, 256, SMEMB>>>(3, 4, 5, 1, C0, C1, C2,  C3,  -1, WM_Q0, WM_ALWAYS);

    // q = max(s-1,0) squarings; per-t gating inside kernel; ping-pong 5<->4
    // intermediate squarings: limbs only; final squaring per t: fp32 only
    for (int i = 0; i < S_ITERS; i++) {
        int src = (i & 1) ? 4 : 5;
        int dst = (i & 1) ? 5 : 4;
        gemm_mma<<<gG, 256, SMEMB>>>(src, src, dst, 0, 0,0,0,0, i, WM_LAST, WM_NOTLAST);
    }

    frob_kernel<<<NT, 256>>>();
    final_kernel<<<1, 128>>>(out);
}

// round 12
// speedup vs baseline: 1.0641x; 1.0641x over previous
#include <cuda_runtime.h>
#include <cuda_fp16.h>
#include <math.h>
#include <stdint.h>

#define N 768
#define NT 50
#define NN (N*N)
#define SIGMA 0.1f
#define RES 100
#define NL 5
#define S_ITERS 11      // s <= 12 -> q <= 11 -> active iters i <= 10
#define KC 32
#define NCHUNK (N/KC)   // 24

// Taylor coefficients 1/k!
#define C0  1.0f
#define C1  1.0f
#define C2  0.5f
#define C3  (1.0f/6.0f)
#define C4  (1.0f/24.0f)
#define C5  (1.0f/120.0f)
#define C6  (1.0f/720.0f)
#define C7  (1.0f/5040.0f)
#define C8  (1.0f/40320.0f)
#define C9  (1.0f/362880.0f)
#define C10 (1.0f/3628800.0f)
#define C11 (1.0f/39916800.0f)
#define C12 (2.0876757e-9f)
#define C13 (1.6059044e-10f)
#define C14 (1.1470746e-11f)
#define C15 (7.6471637e-13f)

// epilogue write modes
#define WM_NEVER   0
#define WM_ALWAYS  1
#define WM_NOTLAST 2   // iff iter < q-1
// fused reduction modes
#define RD_NONE  0
#define RD_SQ    1     // frob if iter == q-1 (last squaring)
#define RD_FINAL 2     // if q==0: s==0 ? trace : frob (final exp launch)

// ---------------- global scratch ----------------
__device__ float g_dist[NN];
__device__ float g_r[NT*N];
__device__ float g_rmax[NT];
__device__ int   g_s[NT];
__device__ int   g_q[NT];
__device__ float g_scale[NT];
__device__ float g_maxdist;
__device__ float g_betti[NT];
// fp32 buffers: 0=M 1=M2 2=M3 3=M4 4/5 = ping-pong
// g_buf[5] doubles as the sigmoid cache between adj_rowsum and buildM
// (first re-written only at the PS stage, strictly after buildM consumes it).
__device__ float g_buf[6][(size_t)NT*NN];
// fp16 limb planes (2 per buffer); 16B-aligned for cp.async/uint2
__device__ __align__(16) __half g_limb[6][2][(size_t)NT*NN];

// ---------------- helpers ----------------
__device__ __forceinline__ void atomicMaxF(float* addr, float v) {
    atomicMax((int*)addr, __float_as_int(v));   // non-negative floats
}
__device__ __forceinline__ uint32_t smem_u32(const void* p) {
    uint32_t a;
    asm("{ .reg .u64 t; cvta.to.shared.u64 t, %1; cvt.u32.u64 %0, t; }" : "=r"(a) : "l"(p));
    return a;
}
__device__ __forceinline__ void cp16(uint32_t s, const void* g) {
    asm volatile("cp.async.cg.shared.global [%0], [%1], 16;" :: "r"(s), "l"(g));
}
#define CP_COMMIT() asm volatile("cp.async.commit_group;" ::: "memory")
#define CP_WAIT(n)  asm volatile("cp.async.wait_group %0;" :: "n"(n) : "memory")

__device__ __forceinline__ void ldm_x4(uint32_t* r, uint32_t addr) {
    asm volatile("ldmatrix.sync.aligned.m8n8.x4.shared.b16 {%0,%1,%2,%3}, [%4];"
                 : "=r"(r[0]), "=r"(r[1]), "=r"(r[2]), "=r"(r[3]) : "r"(addr));
}
__device__ __forceinline__ void mma16816(float* d, const uint32_t* a, const uint32_t* b) {
    asm volatile(
        "mma.sync.aligned.m16n8k16.row.col.f32.f16.f16.f32 "
        "{%0,%1,%2,%3}, {%4,%5,%6,%7}, {%8,%9}, {%0,%1,%2,%3};"
        : "+f"(d[0]), "+f"(d[1]), "+f"(d[2]), "+f"(d[3])
        : "r"(a[0]), "r"(a[1]), "r"(a[2]), "r"(a[3]), "r"(b[0]), "r"(b[1]));
}

__device__ __forceinline__ uint32_t packh(__half lo, __half hi) {
    __half2 t = __halves2half2(lo, hi);
    return *reinterpret_cast<uint32_t*>(&t);
}
__device__ __forceinline__ void split2(float x, __half& h0, __half& h1) {
    h0 = __float2half_rn(x);
    h1 = __float2half_rn(x - __half2float(h0));
}
__device__ __forceinline__ void split2x4(float4 v, uint2& L0, uint2& L1) {
    __half a0,a1,b0,b1,c0,c1,d0,d1;
    split2(v.x, a0,a1); split2(v.y, b0,b1);
    split2(v.z, c0,c1); split2(v.w, d0,d1);
    L0 = make_uint2(packh(a0,b0), packh(c0,d0));
    L1 = make_uint2(packh(a1,b1), packh(c1,d1));
}

// ---------------- small kernels ----------------
__global__ void init_kernel() {
    int t = threadIdx.x;
    if (t < NT) { g_rmax[t] = 0.0f; g_betti[t] = 0.0f; }
    if (t == 0) g_maxdist = 0.0f;
}

__global__ void dist_kernel(const float* __restrict__ pts) {
    __shared__ float p[N*3];
    for (int i = threadIdx.x; i < N*3; i += blockDim.x) p[i] = pts[i];
    __syncthreads();
    int idx = blockIdx.x * blockDim.x + threadIdx.x;
    float d = 0.0f;
    if (idx < NN) {
        int i = idx / N, j = idx - i*N;
        float dx = p[i*3+0] - p[j*3+0];
        float dy = p[i*3+1] - p[j*3+1];
        float dz = p[i*3+2] - p[j*3+2];
        d = sqrtf(dx*dx + dy*dy + dz*dz);
        g_dist[idx] = d;
    }
    __shared__ float red[256];
    red[threadIdx.x] = d;
    __syncthreads();
    for (int off = 128; off > 0; off >>= 1) {
        if (threadIdx.x < off) red[threadIdx.x] = fmaxf(red[threadIdx.x], red[threadIdx.x+off]);
        __syncthreads();
    }
    if (threadIdx.x == 0) atomicMaxF(&g_maxdist, red[0]);
}

// one block per (t, i): sigmoid row computed ONCE, cached in g_buf[5];
// reduces the off-diagonal row sum.
__global__ void adj_rowsum_kernel() {
    int bid = blockIdx.x;           // t*N + i
    int t = bid / N, i = bid - t*N;
    float th = ((float)t / (float)(NT-1)) * g_maxdist;
    const float* drow = g_dist + (size_t)i*N;
    float* arow = g_buf[5] + (size_t)t*NN + (size_t)i*N;
    float s = 0.0f;
    for (int j = threadIdx.x; j < N; j += blockDim.x) {
        float e = expf((drow[j] - th) / SIGMA);
        float a = 1.0f / (1.0f + e);
        arow[j] = a;
        if (j != i) s += a;
    }
    __shared__ float red[128];
    red[threadIdx.x] = s;
    __syncthreads();
    for (int off = 64; off > 0; off >>= 1) {
        if (threadIdx.x < off) red[threadIdx.x] += red[threadIdx.x+off];
        __syncthreads();
    }
    if (threadIdx.x == 0) {
        g_r[bid] = red[0];
        atomicMaxF(&g_rmax[t], red[0]);
    }
}

// Gershgorin bound: lambda_max(L) <= 2*max_row_sum. The slack is load-bearing
// (round-8 post-mortem): it keeps true ||M|| ~ theta/2 for the fp16-limb chain.
__global__ void sq_kernel() {
    int t = threadIdx.x;
    if (t < NT) {
        float x = 2.0f * g_rmax[t] / SIGMA;
        int s = 0;
        if (x > 4.0f) s = (int)ceilf(log2f(x * 0.25f));   // scale to ||M|| <= 4
        if (s < 0) s = 0;
        if (s > 12) s = 12;
        g_s[t] = s;
        g_q[t] = (s > 1) ? (s - 1) : 0;
        g_scale[t] = exp2f((float)(-s)) / SIGMA;
    }
}

// M = -L/(sigma*2^s) from the cached adjacency; also emit fp16 limbs of M
__global__ void buildM_kernel() {
    int t = blockIdx.y;
    int idx = blockIdx.x * blockDim.x + threadIdx.x;
    if (idx >= NN) return;
    int i = idx / N, j = idx - i*N;
    float sc = g_scale[t];
    size_t o = (size_t)t*NN + idx;
    float v = (i == j) ? (-g_r[t*N + i] * sc) : (g_buf[5][o] * sc);
    g_buf[0][o] = v;
    __half h0, h1;
    split2(v, h0, h1);
    g_limb[0][0][o] = h0; g_limb[0][1][o] = h1;
}

// buf4 = C12*I + C13*M + C14*M2 + C15*M3 (limbs only)
__global__ void elw_g3_kernel() {
    int t = blockIdx.y;
    int idx = blockIdx.x * blockDim.x + threadIdx.x;
    if (idx >= NN) return;
    int i = idx / N, j = idx - i*N;
    size_t o = (size_t)t*NN + idx;
    float v = C13*g_buf[0][o] + C14*g_buf[1][o] + C15*g_buf[2][o];
    if (i == j) v += C12;
    __half h0, h1;
    split2(v, h0, h1);
    g_limb[4][0][o] = h0; g_limb[4][1][o] = h1;
}

// ---------------- mma.sync batched GEMM (fp16 2-limb, 3 products) ----------------
// smem: 2 buffers x 4 limb tiles (A0 A1 B0 B1); tile = 128 rows x 32 fp16, pitch 80B
#define TILEB 10240          // 128*80
#define BUFB  (4*TILEB)      // 40960
#define SMEMB (2*BUFB)       // 81920
#define CPIT  132            // C_sm pitch (floats); multiple of 4 -> 16B rows

// merged==1: gridDim.z = 2*NT; op 0 = (1,0,2) fp32-only (M3), op 1 = (1,1,3) limbs-only (M4)
__global__ void __launch_bounds__(256, 2) gemm_mma(int ai, int bi, int ci, int addG,
                                                   float gc0, float gc1, float gc2, float gc3,
                                                   int iter, int fmode, int lmode,
                                                   int rmode, int merged)
{
    int t, op = 0;
    if (merged) { t = blockIdx.z % NT; op = blockIdx.z / NT; }
    else t = blockIdx.z;
    if (merged && op == 1) { ai = 1; bi = 1; ci = 3; fmode = WM_NEVER; lmode = WM_ALWAYS; }

    int q = g_q[t];
    if (iter >= 0 && iter >= q) return;

    bool wF = (fmode == WM_ALWAYS);
    bool wL = (lmode == WM_ALWAYS) || (lmode == WM_NOTLAST && iter < q-1);
    // fused reduction kind: 0 none, 1 trace, 2 frob
    int rkind = 0;
    if (rmode == RD_SQ && iter == q-1) rkind = 2;
    else if (rmode == RD_FINAL && q == 0) rkind = (g_s[t] == 0) ? 1 : 2;

    // lower-triangular tile decode (21 tiles of 6x6)
    int r = 0, rem = blockIdx.x;
    while (rem > r) { rem -= (r + 1); r++; }
    int btr = r, btc = rem;            // tile row >= tile col
    int row0 = btr * 128, col0 = btc * 128;

    extern __shared__ char smem[];
    uint32_t sb = smem_u32(smem);
    int tid = threadIdx.x;
    int wid = tid >> 5, lane = tid & 31;
    int wm = wid >> 2, wn = wid & 3;   // warp tile: rows wm*64, cols wn*32

    bool same = (ai == bi) && (btr == btc);
    const __half* pA[2] = { g_limb[ai][0] + (size_t)t*NN, g_limb[ai][1] + (size_t)t*NN };
    const __half* pB[2] = { g_limb[bi][0] + (size_t)t*NN, g_limb[bi][1] + (size_t)t*NN };
    float* C = g_buf[ci] + (size_t)t*NN;

    float acc[4][4][4];
    #pragma unroll
    for (int a = 0; a < 4; a++)
        #pragma unroll
        for (int b = 0; b < 4; b++)
            #pragma unroll
            for (int c = 0; c < 4; c++) acc[a][b][c] = 0.0f;

    // lane-invariant ldmatrix offsets
    uint32_t aLane = (uint32_t)((wm*64 + (lane & 15))*80 + ((lane >> 4)*16));
    uint32_t bLane = (uint32_t)((wn*32 + (lane & 7) + ((lane >> 4) << 3))*80 + (((lane >> 3) & 1)*16));
    const int nTiles = same ? 2 : 4;
    const int totCp = nTiles * 512;

    // ---- async-copy producer ----
    auto issue = [&](int c, int buf) {
        uint32_t bb = sb + buf*BUFB;
        int cK = c*KC;
        for (int idx = tid; idx < totCp; idx += 256) {
            int tile = idx >> 9;
            int rr2 = (idx & 511) >> 2, q2 = idx & 3;
            const __half* src = (tile < 2)
                ? pA[tile] + (size_t)(row0 + rr2)*N + cK + q2*8
                : pB[tile-2] + (size_t)(col0 + rr2)*N + cK + q2*8;
            cp16(bb + tile*TILEB + rr2*80 + q2*16, src);
        }
    };

    issue(0, 0); CP_COMMIT();

    for (int c = 0; c < NCHUNK; c++) {
        if (c + 1 < NCHUNK) { issue(c+1, (c+1)&1); CP_COMMIT(); CP_WAIT(1); }
        else CP_WAIT(0);
        __syncthreads();

        uint32_t bb  = sb + (c&1)*BUFB;
        uint32_t bbB = same ? bb : bb + 2*TILEB;
        #pragma unroll
        for (int ks = 0; ks < 2; ks++) {
            uint32_t af0[4][4], af1[4][4], bf0[2][4], bf1[2][4];
            {
                uint32_t base = bbB + bLane + ks*32;
                ldm_x4(bf0[0], base);            ldm_x4(bf0[1], base + 16*80);
                ldm_x4(bf1[0], base + TILEB);    ldm_x4(bf1[1], base + TILEB + 16*80);
            }
            {
                uint32_t base = bb + aLane + ks*32;
                #pragma unroll
                for (int mt = 0; mt < 4; mt++) {
                    ldm_x4(af0[mt], base + mt*16*80);
                    ldm_x4(af1[mt], base + TILEB + mt*16*80);
                }
            }
            // 3 limb products, product-first
            #pragma unroll
            for (int mt = 0; mt < 4; mt++)
                #pragma unroll
                for (int nt = 0; nt < 4; nt++)
                    mma16816(acc[mt][nt], af0[mt], &bf0[nt>>1][(nt&1)*2]);
            #pragma unroll
            for (int mt = 0; mt < 4; mt++)
                #pragma unroll
                for (int nt = 0; nt < 4; nt++)
                    mma16816(acc[mt][nt], af0[mt], &bf1[nt>>1][(nt&1)*2]);
            #pragma unroll
            for (int mt = 0; mt < 4; mt++)
                #pragma unroll
                for (int nt = 0; nt < 4; nt++)
                    mma16816(acc[mt][nt], af1[mt], &bf0[nt>>1][(nt&1)*2]);
        }
        __syncthreads();
    }

    // ---- epilogue via smem ----
    float* C_sm = (float*)smem;
    {
        int g = lane >> 2, j2 = (lane & 3) * 2;
        #pragma unroll
        for (int mt = 0; mt < 4; mt++)
            #pragma unroll
            for (int nt = 0; nt < 4; nt++) {
                int rr = wm*64 + mt*16 + g;
                int cc = wn*32 + nt*8 + j2;
                C_sm[rr*CPIT + cc]       = acc[mt][nt][0];
                C_sm[rr*CPIT + cc + 1]   = acc[mt][nt][1];
                C_sm[(rr+8)*CPIT + cc]   = acc[mt][nt][2];
                C_sm[(rr+8)*CPIT + cc+1] = acc[mt][nt][3];
            }
    }
    __syncthreads();

    const float* Mp  = g_buf[0] + (size_t)t*NN;
    const float* M2p = g_buf[1] + (size_t)t*NN;
    const float* M3p = g_buf[2] + (size_t)t*NN;
    __half* L0 = g_limb[ci][0] + (size_t)t*NN;
    __half* L1 = g_limb[ci][1] + (size_t)t*NN;

    float rsum = 0.0f;
    {   // phase A: lower tile, row-coalesced
        int rr = tid & 127, h = tid >> 7;
        size_t rowOff = (size_t)(row0 + rr)*N + col0;
        float w = (btr == btc) ? 1.0f : 2.0f;   // frob mirror weight
        #pragma unroll
        for (int i = 0; i < 16; i++) {
            int ce = h*64 + i*4;
            float4 v = *(float4*)&C_sm[rr*CPIT + ce];
            if (addG) {
                float4 m1 = *(const float4*)(Mp  + rowOff + ce);
                float4 m2 = *(const float4*)(M2p + rowOff + ce);
                float4 m3 = *(const float4*)(M3p + rowOff + ce);
                v.x += gc1*m1.x + gc2*m2.x + gc3*m3.x;
                v.y += gc1*m1.y + gc2*m2.y + gc3*m3.y;
                v.z += gc1*m1.z + gc2*m2.z + gc3*m3.z;
                v.w += gc1*m1.w + gc2*m2.w + gc3*m3.w;
                if (btr == btc) {
                    int k = rr - ce;
                    if (k >= 0 && k < 4) (&v.x)[k] += gc0;
                }
                if (btr != btc) *(float4*)&C_sm[rr*CPIT + ce] = v;  // mirror reads adjusted
            }
            if (wF) *(float4*)(C + rowOff + ce) = v;
            if (wL) {
                uint2 l0, l1;
                split2x4(v, l0, l1);
                *(uint2*)(L0 + rowOff + ce) = l0;
                *(uint2*)(L1 + rowOff + ce) = l1;
            }
            if (rkind == 2) {
                rsum += w * (v.x*v.x + v.y*v.y + v.z*v.z + v.w*v.w);
            } else if (rkind == 1) {
                if (btr == btc) {
                    int k = rr - ce;
                    if (k >= 0 && k < 4) rsum += (&v.x)[k];
                }
            }
        }
    }
    if (btr != btc && (wF || wL)) {   // phase B: mirror (transpose out of smem)
        __syncthreads();
        int u = tid >> 1, hh = tid & 1;
        size_t rowOff = (size_t)(col0 + u)*N + row0;
        #pragma unroll
        for (int i = 0; i < 16; i++) {
            int x0 = hh*64 + i*4;
            float4 v = make_float4(C_sm[(x0  )*CPIT + u], C_sm[(x0+1)*CPIT + u],
                                   C_sm[(x0+2)*CPIT + u], C_sm[(x0+3)*CPIT + u]);
            if (wF) *(float4*)(C + rowOff + x0) = v;
            if (wL) {
                uint2 l0, l1;
                split2x4(v, l0, l1);
                *(uint2*)(L0 + rowOff + x0) = l0;
                *(uint2*)(L1 + rowOff + x0) = l1;
            }
        }
    }
    // fused betti reduction (uniform predicate across block)
    if (rkind) {
        __shared__ float redsm[256];
        redsm[tid] = rsum;
        __syncthreads();
        for (int off = 128; off > 0; off >>= 1) {
            if (tid < off) redsm[tid] += redsm[tid + off];
            __syncthreads();
        }
        if (tid == 0) atomicAdd(&g_betti[t], redsm[0]);
    }
}

__global__ void final_kernel(float* __restrict__ out) {
    __shared__ float b[NT];
    __shared__ float bi[RES], sm[RES], dv[RES];
    __shared__ float red;
    int tid = threadIdx.x;
    if (tid < NT) b[tid] = g_betti[tid];
    __syncthreads();
    if (tid < RES) {
        float pos = (float)(NT-1) * (float)tid / (float)(RES-1);
        int i0 = (int)floorf(pos);
        if (i0 > NT-2) i0 = NT-2;
        if (i0 < 0) i0 = 0;
        float fr = pos - (float)i0;
        bi[tid] = b[i0]*(1.0f - fr) + b[i0+1]*fr;
    }
    __syncthreads();
    if (tid == 0) {
        float m = bi[0];
        for (int i = 1; i < RES; i++) m = fmaxf(m, bi[i]);
        red = m;
    }
    __syncthreads();
    if (tid < RES) out[tid] = bi[tid] / (red + 1e-8f);

    for (int k = 1; k < NL; k++) {
        int ks = 2*k + 1;
        int pad = ks / 2;
        __syncthreads();
        if (tid < RES) {
            float s = 0.0f;
            for (int u = -pad; u <= pad; u++) {
                int j = tid + u;
                j = max(0, min(RES-1, j));
                s += bi[j];
            }
            sm[tid] = s / (float)ks;
        }
        __syncthreads();
        if (tid < RES) {
            float d = (tid < RES-1) ? (sm[tid+1] - sm[tid]) : (sm[RES-1] - sm[RES-2]);
            dv[tid] = d;
        }
        __syncthreads();
        if (tid == 0) {
            float m = fabsf(dv[0]);
            for (int i = 1; i < RES; i++) m = fmaxf(m, fabsf(dv[i]));
            red = m;
        }
        __syncthreads();
        if (tid < RES) out[k*RES + tid] = dv[tid] / (red + 1e-8f);
    }
}

extern "C" void kernel_launch(void* const* d_in, const int* in_sizes, int n_in,
                              void* d_out, int out_size)
{
    const float* pts = (const float*)d_in[0];
    float* out = (float*)d_out;

    cudaFuncSetAttribute(gemm_mma, cudaFuncAttributeMaxDynamicSharedMemorySize, SMEMB);

    init_kernel<<<1, 64>>>();
    dist_kernel<<<NN/256, 256>>>(pts);
    adj_rowsum_kernel<<<NT*N, 128>>>();
    sq_kernel<<<1, 64>>>();

    dim3 gE(NN/256, NT);
    buildM_kernel<<<gE, 256>>>();

    dim3 gG(21, 1, NT);
    dim3 gG2(21, 1, 2*NT);
    // Taylor degree 15, Paterson-Stockmeyer q=4
    // M2: fp32 (elw_g3 + addG read it) + limbs
    gemm_mma<<<gG, 256, SMEMB>>>(0, 0, 1, 0, 0,0,0,0, -1, WM_ALWAYS, WM_ALWAYS, RD_NONE, 0);
    // M3 (fp32 only) + M4 (limbs only) merged into one launch
    gemm_mma<<<gG2, 256, SMEMB>>>(1, 0, 2, 0, 0,0,0,0, -1, WM_ALWAYS, WM_NEVER, RD_NONE, 1);
    elw_g3_kernel<<<gE, 256>>>();   // B4 limbs = G3
    // PS intermediates: limbs only
    gemm_mma<<<gG, 256, SMEMB>>>(3, 4, 5, 1, C8, C9, C10, C11, -1, WM_NEVER, WM_ALWAYS, RD_NONE, 0);
    gemm_mma<<<gG, 256, SMEMB>>>(3, 5, 4, 1, C4, C5, C6,  C7,  -1, WM_NEVER, WM_ALWAYS, RD_NONE, 0);
    // exp(M): limbs (squaring operand); fused trace/frob for q==0 t
    gemm_mma<<<gG, 256, SMEMB>>>(3, 4, 5, 1, C0, C1, C2,  C3,  -1, WM_NEVER, WM_ALWAYS, RD_FINAL, 0);

    // q squarings; last iteration per t fuses the frob reduction, writes nothing
    for (int i = 0; i < S_ITERS; i++) {
        int src = (i & 1) ? 4 : 5;
        int dst = (i & 1) ? 5 : 4;
        gemm_mma<<<gG, 256, SMEMB>>>(src, src, dst, 0, 0,0,0,0, i, WM_NEVER, WM_NOTLAST, RD_SQ, 0);
    }

    final_kernel<<<1, 128>>>(out);
}

// round 13
// speedup vs baseline: 1.0727x; 1.0081x over previous
#include <cuda_runtime.h>
#include <cuda_fp16.h>
#include <math.h>
#include <stdint.h>

#define N 768
#define NT 50
#define NN (N*N)
#define SIGMA 0.1f
#define RES 100
#define NL 5
#define KC 32
#define NCHUNK (N/KC)   // 24
#define NCTA 296        // 148 SMs x occ 2 - all co-resident (required for grid barrier)
#define NSTAGES 17

// Taylor coefficients 1/k!
#define C0  1.0f
#define C1  1.0f
#define C2  0.5f
#define C3  (1.0f/6.0f)
#define C4  (1.0f/24.0f)
#define C5  (1.0f/120.0f)
#define C6  (1.0f/720.0f)
#define C7  (1.0f/5040.0f)
#define C8  (1.0f/40320.0f)
#define C9  (1.0f/362880.0f)
#define C10 (1.0f/3628800.0f)
#define C11 (1.0f/39916800.0f)
#define C12 (2.0876757e-9f)
#define C13 (1.6059044e-10f)
#define C14 (1.1470746e-11f)
#define C15 (7.6471637e-13f)

// epilogue write modes
#define WM_NEVER   0
#define WM_ALWAYS  1
#define WM_NOTLAST 2   // iff iter < q-1
// fused reduction modes
#define RD_NONE  0
#define RD_SQ    1     // frob if iter == q-1 (last squaring)
#define RD_FINAL 2     // if q==0: s==0 ? trace : frob (final exp launch)

// ---------------- global scratch ----------------
__device__ float g_dist[NN];
__device__ float g_r[NT*N];
__device__ float g_rmax[NT];
__device__ int   g_s[NT];
__device__ int   g_q[NT];
__device__ float g_scale[NT];
__device__ float g_maxdist;
__device__ float g_betti[NT];
__device__ unsigned g_ticket[NSTAGES];
__device__ unsigned g_bar[NSTAGES];
// fp32 buffers: 0=M 1=M2 2=M3 3=M4 4/5 = ping-pong
// g_buf[5] doubles as the sigmoid cache between adj_rowsum and buildM.
__device__ float g_buf[6][(size_t)NT*NN];
// fp16 limb planes (2 per buffer); 16B-aligned for cp.async/uint2
__device__ __align__(16) __half g_limb[6][2][(size_t)NT*NN];

// stage table: the whole GEMM chain as one persistent kernel
struct StageDesc {
    int kind;      // 0 = gemm, 1 = elw_g3
    int ai, bi, ci, addG;
    int iter, fm, lm, rm, units, merged;
    float g0, g1, g2, g3;
};
__device__ const StageDesc g_stg[NSTAGES] = {
    {0, 0,0,1, 0, -1, WM_ALWAYS, WM_ALWAYS, RD_NONE, 1050, 0, 0,0,0,0},        // M2
    {0, 1,0,2, 0, -1, WM_ALWAYS, WM_NEVER,  RD_NONE, 2100, 1, 0,0,0,0},        // M3 + M4 merged
    {1, 0,0,0, 0, -1, 0, 0, 0,               1800, 0, 0,0,0,0},                // G3 elementwise
    {0, 3,4,5, 1, -1, WM_NEVER, WM_ALWAYS,  RD_NONE, 1050, 0, C8,C9,C10,C11},  // PS1
    {0, 3,5,4, 1, -1, WM_NEVER, WM_ALWAYS,  RD_NONE, 1050, 0, C4,C5,C6,C7},    // PS2
    {0, 3,4,5, 1, -1, WM_NEVER, WM_ALWAYS,  RD_FINAL,1050, 0, C0,C1,C2,C3},    // PS3 = exp(M)
    {0, 5,5,4, 0,  0, WM_NEVER, WM_NOTLAST, RD_SQ,   1050, 0, 0,0,0,0},        // sq i=0
    {0, 4,4,5, 0,  1, WM_NEVER, WM_NOTLAST, RD_SQ,   1050, 0, 0,0,0,0},
    {0, 5,5,4, 0,  2, WM_NEVER, WM_NOTLAST, RD_SQ,   1050, 0, 0,0,0,0},
    {0, 4,4,5, 0,  3, WM_NEVER, WM_NOTLAST, RD_SQ,   1050, 0, 0,0,0,0},
    {0, 5,5,4, 0,  4, WM_NEVER, WM_NOTLAST, RD_SQ,   1050, 0, 0,0,0,0},
    {0, 4,4,5, 0,  5, WM_NEVER, WM_NOTLAST, RD_SQ,   1050, 0, 0,0,0,0},
    {0, 5,5,4, 0,  6, WM_NEVER, WM_NOTLAST, RD_SQ,   1050, 0, 0,0,0,0},
    {0, 4,4,5, 0,  7, WM_NEVER, WM_NOTLAST, RD_SQ,   1050, 0, 0,0,0,0},
    {0, 5,5,4, 0,  8, WM_NEVER, WM_NOTLAST, RD_SQ,   1050, 0, 0,0,0,0},
    {0, 4,4,5, 0,  9, WM_NEVER, WM_NOTLAST, RD_SQ,   1050, 0, 0,0,0,0},
    {0, 5,5,4, 0, 10, WM_NEVER, WM_NOTLAST, RD_SQ,   1050, 0, 0,0,0,0},        // sq i=10 (q<=11)
};

// ---------------- helpers ----------------
__device__ __forceinline__ void atomicMaxF(float* addr, float v) {
    atomicMax((int*)addr, __float_as_int(v));   // non-negative floats
}
__device__ __forceinline__ uint32_t smem_u32(const void* p) {
    uint32_t a;
    asm("{ .reg .u64 t; cvta.to.shared.u64 t, %1; cvt.u32.u64 %0, t; }" : "=r"(a) : "l"(p));
    return a;
}
__device__ __forceinline__ void cp16(uint32_t s, const void* g) {
    asm volatile("cp.async.cg.shared.global [%0], [%1], 16;" :: "r"(s), "l"(g));
}
#define CP_COMMIT() asm volatile("cp.async.commit_group;" ::: "memory")
#define CP_WAIT(n)  asm volatile("cp.async.wait_group %0;" :: "n"(n) : "memory")

__device__ __forceinline__ void ldm_x4(uint32_t* r, uint32_t addr) {
    asm volatile("ldmatrix.sync.aligned.m8n8.x4.shared.b16 {%0,%1,%2,%3}, [%4];"
                 : "=r"(r[0]), "=r"(r[1]), "=r"(r[2]), "=r"(r[3]) : "r"(addr));
}
__device__ __forceinline__ void mma16816(float* d, const uint32_t* a, const uint32_t* b) {
    asm volatile(
        "mma.sync.aligned.m16n8k16.row.col.f32.f16.f16.f32 "
        "{%0,%1,%2,%3}, {%4,%5,%6,%7}, {%8,%9}, {%0,%1,%2,%3};"
        : "+f"(d[0]), "+f"(d[1]), "+f"(d[2]), "+f"(d[3])
        : "r"(a[0]), "r"(a[1]), "r"(a[2]), "r"(a[3]), "r"(b[0]), "r"(b[1]));
}

__device__ __forceinline__ uint32_t packh(__half lo, __half hi) {
    __half2 t = __halves2half2(lo, hi);
    return *reinterpret_cast<uint32_t*>(&t);
}
__device__ __forceinline__ void split2(float x, __half& h0, __half& h1) {
    h0 = __float2half_rn(x);
    h1 = __float2half_rn(x - __half2float(h0));
}
__device__ __forceinline__ void split2x4(float4 v, uint2& L0, uint2& L1) {
    __half a0,a1,b0,b1,c0,c1,d0,d1;
    split2(v.x, a0,a1); split2(v.y, b0,b1);
    split2(v.z, c0,c1); split2(v.w, d0,d1);
    L0 = make_uint2(packh(a0,b0), packh(c0,d0));
    L1 = make_uint2(packh(a1,b1), packh(c1,d1));
}

// ---------------- preamble kernels ----------------
__global__ void init_kernel() {
    int t = threadIdx.x;
    if (t < NT) { g_rmax[t] = 0.0f; g_betti[t] = 0.0f; }
    if (t < NSTAGES) { g_ticket[t] = 0u; g_bar[t] = 0u; }
    if (t == 0) g_maxdist = 0.0f;
}

__global__ void dist_kernel(const float* __restrict__ pts) {
    __shared__ float p[N*3];
    for (int i = threadIdx.x; i < N*3; i += blockDim.x) p[i] = pts[i];
    __syncthreads();
    int idx = blockIdx.x * blockDim.x + threadIdx.x;
    float d = 0.0f;
    if (idx < NN) {
        int i = idx / N, j = idx - i*N;
        float dx = p[i*3+0] - p[j*3+0];
        float dy = p[i*3+1] - p[j*3+1];
        float dz = p[i*3+2] - p[j*3+2];
        d = sqrtf(dx*dx + dy*dy + dz*dz);
        g_dist[idx] = d;
    }
    __shared__ float red[256];
    red[threadIdx.x] = d;
    __syncthreads();
    for (int off = 128; off > 0; off >>= 1) {
        if (threadIdx.x < off) red[threadIdx.x] = fmaxf(red[threadIdx.x], red[threadIdx.x+off]);
        __syncthreads();
    }
    if (threadIdx.x == 0) atomicMaxF(&g_maxdist, red[0]);
}

// sigmoid row computed ONCE, cached in g_buf[5]; off-diagonal row sum reduced.
__global__ void adj_rowsum_kernel() {
    int bid = blockIdx.x;           // t*N + i
    int t = bid / N, i = bid - t*N;
    float th = ((float)t / (float)(NT-1)) * g_maxdist;
    const float* drow = g_dist + (size_t)i*N;
    float* arow = g_buf[5] + (size_t)t*NN + (size_t)i*N;
    float s = 0.0f;
    for (int j = threadIdx.x; j < N; j += blockDim.x) {
        float e = expf((drow[j] - th) / SIGMA);
        float a = 1.0f / (1.0f + e);
        arow[j] = a;
        if (j != i) s += a;
    }
    __shared__ float red[128];
    red[threadIdx.x] = s;
    __syncthreads();
    for (int off = 64; off > 0; off >>= 1) {
        if (threadIdx.x < off) red[threadIdx.x] += red[threadIdx.x+off];
        __syncthreads();
    }
    if (threadIdx.x == 0) {
        g_r[bid] = red[0];
        atomicMaxF(&g_rmax[t], red[0]);
    }
}

// Gershgorin bound: lambda_max(L) <= 2*max_row_sum. Slack is load-bearing
// (round-8 post-mortem): keeps true ||M|| ~ theta/2 for the fp16-limb chain.
__global__ void sq_kernel() {
    int t = threadIdx.x;
    if (t < NT) {
        float x = 2.0f * g_rmax[t] / SIGMA;
        int s = 0;
        if (x > 4.0f) s = (int)ceilf(log2f(x * 0.25f));   // scale to ||M|| <= 4
        if (s < 0) s = 0;
        if (s > 12) s = 12;
        g_s[t] = s;
        g_q[t] = (s > 1) ? (s - 1) : 0;
        g_scale[t] = exp2f((float)(-s)) / SIGMA;
    }
}

// M = -L/(sigma*2^s) from the cached adjacency; also emit fp16 limbs of M
__global__ void buildM_kernel() {
    int t = blockIdx.y;
    int idx = blockIdx.x * blockDim.x + threadIdx.x;
    if (idx >= NN) return;
    int i = idx / N, j = idx - i*N;
    float sc = g_scale[t];
    size_t o = (size_t)t*NN + idx;
    float v = (i == j) ? (-g_r[t*N + i] * sc) : (g_buf[5][o] * sc);
    g_buf[0][o] = v;
    __half h0, h1;
    split2(v, h0, h1);
    g_limb[0][0][o] = h0; g_limb[0][1][o] = h1;
}

// ---------------- persistent mega-kernel ----------------
#define TILEB 10240          // 128*80
#define BUFB  (4*TILEB)      // 40960
#define SMEMB (2*BUFB)       // 81920
#define CPIT  132            // C_sm pitch (floats); multiple of 4 -> 16B rows

__device__ void gemm_unit(const StageDesc& st, int u, int tid, char* smem, uint32_t sb)
{
    int op = 0;
    if (st.merged) { op = u / 1050; u -= op * 1050; }
    int t = u / 21, tileIdx = u - t*21;
    int ai = st.ai, bi = st.bi, ci = st.ci, fm = st.fm, lm = st.lm;
    if (op == 1) { ai = 1; bi = 1; ci = 3; fm = WM_NEVER; lm = WM_ALWAYS; }

    int q = g_q[t];
    if (st.iter >= 0 && st.iter >= q) return;

    bool wF = (fm == WM_ALWAYS);
    bool wL = (lm == WM_ALWAYS) || (lm == WM_NOTLAST && st.iter < q-1);
    int rkind = 0;
    if (st.rm == RD_SQ && st.iter == q-1) rkind = 2;
    else if (st.rm == RD_FINAL && q == 0) rkind = (g_s[t] == 0) ? 1 : 2;

    // lower-triangular tile decode (21 tiles of 6x6)
    int r = 0, rem = tileIdx;
    while (rem > r) { rem -= (r + 1); r++; }
    int btr = r, btc = rem;            // tile row >= tile col
    int row0 = btr * 128, col0 = btc * 128;

    int wid = tid >> 5, lane = tid & 31;
    int wm = wid >> 2, wn = wid & 3;

    bool same = (ai == bi) && (btr == btc);
    const __half* pA[2] = { g_limb[ai][0] + (size_t)t*NN, g_limb[ai][1] + (size_t)t*NN };
    const __half* pB[2] = { g_limb[bi][0] + (size_t)t*NN, g_limb[bi][1] + (size_t)t*NN };
    float* C = g_buf[ci] + (size_t)t*NN;

    float acc[4][4][4];
    #pragma unroll
    for (int a = 0; a < 4; a++)
        #pragma unroll
        for (int b = 0; b < 4; b++)
            #pragma unroll
            for (int c = 0; c < 4; c++) acc[a][b][c] = 0.0f;

    uint32_t aLane = (uint32_t)((wm*64 + (lane & 15))*80 + ((lane >> 4)*16));
    uint32_t bLane = (uint32_t)((wn*32 + (lane & 7) + ((lane >> 4) << 3))*80 + (((lane >> 3) & 1)*16));
    const int nTiles = same ? 2 : 4;
    const int totCp = nTiles * 512;

    auto issue = [&](int c, int buf) {
        uint32_t bb = sb + buf*BUFB;
        int cK = c*KC;
        for (int idx = tid; idx < totCp; idx += 256) {
            int tile = idx >> 9;
            int rr2 = (idx & 511) >> 2, q2 = idx & 3;
            const __half* src = (tile < 2)
                ? pA[tile] + (size_t)(row0 + rr2)*N + cK + q2*8
                : pB[tile-2] + (size_t)(col0 + rr2)*N + cK + q2*8;
            cp16(bb + tile*TILEB + rr2*80 + q2*16, src);
        }
    };

    issue(0, 0); CP_COMMIT();

    for (int c = 0; c < NCHUNK; c++) {
        if (c + 1 < NCHUNK) { issue(c+1, (c+1)&1); CP_COMMIT(); CP_WAIT(1); }
        else CP_WAIT(0);
        __syncthreads();

        uint32_t bb  = sb + (c&1)*BUFB;
        uint32_t bbB = same ? bb : bb + 2*TILEB;
        #pragma unroll
        for (int ks = 0; ks < 2; ks++) {
            uint32_t af0[4][4], af1[4][4], bf0[2][4], bf1[2][4];
            {
                uint32_t base = bbB + bLane + ks*32;
                ldm_x4(bf0[0], base);            ldm_x4(bf0[1], base + 16*80);
                ldm_x4(bf1[0], base + TILEB);    ldm_x4(bf1[1], base + TILEB + 16*80);
            }
            {
                uint32_t base = bb + aLane + ks*32;
                #pragma unroll
                for (int mt = 0; mt < 4; mt++) {
                    ldm_x4(af0[mt], base + mt*16*80);
                    ldm_x4(af1[mt], base + TILEB + mt*16*80);
                }
            }
            // 3 limb products, product-first
            #pragma unroll
            for (int mt = 0; mt < 4; mt++)
                #pragma unroll
                for (int nt = 0; nt < 4; nt++)
                    mma16816(acc[mt][nt], af0[mt], &bf0[nt>>1][(nt&1)*2]);
            #pragma unroll
            for (int mt = 0; mt < 4; mt++)
                #pragma unroll
                for (int nt = 0; nt < 4; nt++)
                    mma16816(acc[mt][nt], af0[mt], &bf1[nt>>1][(nt&1)*2]);
            #pragma unroll
            for (int mt = 0; mt < 4; mt++)
                #pragma unroll
                for (int nt = 0; nt < 4; nt++)
                    mma16816(acc[mt][nt], af1[mt], &bf0[nt>>1][(nt&1)*2]);
        }
        __syncthreads();
    }

    // ---- epilogue via smem ----
    float* C_sm = (float*)smem;
    {
        int g = lane >> 2, j2 = (lane & 3) * 2;
        #pragma unroll
        for (int mt = 0; mt < 4; mt++)
            #pragma unroll
            for (int nt = 0; nt < 4; nt++) {
                int rr = wm*64 + mt*16 + g;
                int cc = wn*32 + nt*8 + j2;
                C_sm[rr*CPIT + cc]       = acc[mt][nt][0];
                C_sm[rr*CPIT + cc + 1]   = acc[mt][nt][1];
                C_sm[(rr+8)*CPIT + cc]   = acc[mt][nt][2];
                C_sm[(rr+8)*CPIT + cc+1] = acc[mt][nt][3];
            }
    }
    __syncthreads();

    const float* Mp  = g_buf[0] + (size_t)t*NN;
    const float* M2p = g_buf[1] + (size_t)t*NN;
    const float* M3p = g_buf[2] + (size_t)t*NN;
    __half* L0 = g_limb[ci][0] + (size_t)t*NN;
    __half* L1 = g_limb[ci][1] + (size_t)t*NN;

    float rsum = 0.0f;
    {   // phase A: lower tile, row-coalesced
        int rr = tid & 127, h = tid >> 7;
        size_t rowOff = (size_t)(row0 + rr)*N + col0;
        float w = (btr == btc) ? 1.0f : 2.0f;
        #pragma unroll
        for (int i = 0; i < 16; i++) {
            int ce = h*64 + i*4;
            float4 v = *(float4*)&C_sm[rr*CPIT + ce];
            if (st.addG) {
                float4 m1 = *(const float4*)(Mp  + rowOff + ce);
                float4 m2 = *(const float4*)(M2p + rowOff + ce);
                float4 m3 = *(const float4*)(M3p + rowOff + ce);
                v.x += st.g1*m1.x + st.g2*m2.x + st.g3*m3.x;
                v.y += st.g1*m1.y + st.g2*m2.y + st.g3*m3.y;
                v.z += st.g1*m1.z + st.g2*m2.z + st.g3*m3.z;
                v.w += st.g1*m1.w + st.g2*m2.w + st.g3*m3.w;
                if (btr == btc) {
                    int k = rr - ce;
                    if (k >= 0 && k < 4) (&v.x)[k] += st.g0;
                }
                if (btr != btc) *(float4*)&C_sm[rr*CPIT + ce] = v;
            }
            if (wF) *(float4*)(C + rowOff + ce) = v;
            if (wL) {
                uint2 l0, l1;
                split2x4(v, l0, l1);
                *(uint2*)(L0 + rowOff + ce) = l0;
                *(uint2*)(L1 + rowOff + ce) = l1;
            }
            if (rkind == 2) {
                rsum += w * (v.x*v.x + v.y*v.y + v.z*v.z + v.w*v.w);
            } else if (rkind == 1) {
                if (btr == btc) {
                    int k = rr - ce;
                    if (k >= 0 && k < 4) rsum += (&v.x)[k];
                }
            }
        }
    }
    if (btr != btc && (wF || wL)) {   // phase B: mirror
        __syncthreads();
        int u2 = tid >> 1, hh = tid & 1;
        size_t rowOff = (size_t)(col0 + u2)*N + row0;
        #pragma unroll
        for (int i = 0; i < 16; i++) {
            int x0 = hh*64 + i*4;
            float4 v = make_float4(C_sm[(x0  )*CPIT + u2], C_sm[(x0+1)*CPIT + u2],
                                   C_sm[(x0+2)*CPIT + u2], C_sm[(x0+3)*CPIT + u2]);
            if (wF) *(float4*)(C + rowOff + x0) = v;
            if (wL) {
                uint2 l0, l1;
                split2x4(v, l0, l1);
                *(uint2*)(L0 + rowOff + x0) = l0;
                *(uint2*)(L1 + rowOff + x0) = l1;
            }
        }
    }
    if (rkind) {
        __shared__ float redsm[256];
        redsm[tid] = rsum;
        __syncthreads();
        for (int off = 128; off > 0; off >>= 1) {
            if (tid < off) redsm[tid] += redsm[tid + off];
            __syncthreads();
        }
        if (tid == 0) atomicAdd(&g_betti[t], redsm[0]);
    }
    __syncthreads();
}

// G3 elementwise: buf4 limbs = C12*I + C13*M + C14*M2 + C15*M3 on a 128x128 tile
__device__ void elw_unit(int u, int tid)
{
    int t = u / 36, tile = u - t*36;
    int tr = tile / 6, tc = tile - tr*6;
    int rr = tid >> 1, hh = (tid & 1) * 64;
    size_t o = (size_t)t*NN + (size_t)(tr*128 + rr)*N + tc*128 + hh;
    const float* Mp  = g_buf[0];
    const float* M2p = g_buf[1];
    const float* M3p = g_buf[2];
    __half* L0 = g_limb[4][0];
    __half* L1 = g_limb[4][1];
    #pragma unroll
    for (int i = 0; i < 16; i++) {
        float4 m1 = *(const float4*)(Mp  + o + i*4);
        float4 m2 = *(const float4*)(M2p + o + i*4);
        float4 m3 = *(const float4*)(M3p + o + i*4);
        float4 v;
        v.x = C13*m1.x + C14*m2.x + C15*m3.x;
        v.y = C13*m1.y + C14*m2.y + C15*m3.y;
        v.z = C13*m1.z + C14*m2.z + C15*m3.z;
        v.w = C13*m1.w + C14*m2.w + C15*m3.w;
        if (tr == tc) {
            int k = rr - (hh + i*4);
            if (k >= 0 && k < 4) (&v.x)[k] += C12;
        }
        uint2 l0, l1;
        split2x4(v, l0, l1);
        *(uint2*)(L0 + o + i*4) = l0;
        *(uint2*)(L1 + o + i*4) = l1;
    }
}

__global__ void __launch_bounds__(256, 2) mega_kernel()
{
    extern __shared__ char smem[];
    uint32_t sb = smem_u32(smem);
    int tid = threadIdx.x;
    __shared__ int s_unit;

    for (int s = 0; s < NSTAGES; s++) {
        StageDesc st = g_stg[s];
        for (;;) {
            __syncthreads();
            if (tid == 0) s_unit = (int)atomicAdd(&g_ticket[s], 1u);
            __syncthreads();
            int u = s_unit;
            if (u >= st.units) break;
            if (st.kind == 0) gemm_unit(st, u, tid, smem, sb);
            else elw_unit(u, tid);
        }
        // software grid barrier (all NCTA CTAs co-resident by construction)
        if (tid == 0) {
            __threadfence();
            atomicAdd(&g_bar[s], 1u);
            while (*((volatile unsigned*)&g_bar[s]) < NCTA) __nanosleep(64);
            __threadfence();
        }
        __syncthreads();
    }
}

__global__ void final_kernel(float* __restrict__ out) {
    __shared__ float b[NT];
    __shared__ float bi[RES], sm[RES], dv[RES];
    __shared__ float red;
    int tid = threadIdx.x;
    if (tid < NT) b[tid] = g_betti[tid];
    __syncthreads();
    if (tid < RES) {
        float pos = (float)(NT-1) * (float)tid / (float)(RES-1);
        int i0 = (int)floorf(pos);
        if (i0 > NT-2) i0 = NT-2;
        if (i0 < 0) i0 = 0;
        float fr = pos - (float)i0;
        bi[tid] = b[i0]*(1.0f - fr) + b[i0+1]*fr;
    }
    __syncthreads();
    if (tid == 0) {
        float m = bi[0];
        for (int i = 1; i < RES; i++) m = fmaxf(m, bi[i]);
        red = m;
    }
    __syncthreads();
    if (tid < RES) out[tid] = bi[tid] / (red + 1e-8f);

    for (int k = 1; k < NL; k++) {
        int ks = 2*k + 1;
        int pad = ks / 2;
        __syncthreads();
        if (tid < RES) {
            float s = 0.0f;
            for (int u = -pad; u <= pad; u++) {
                int j = tid + u;
                j = max(0, min(RES-1, j));
                s += bi[j];
            }
            sm[tid] = s / (float)ks;
        }
        __syncthreads();
        if (tid < RES) {
            float d = (tid < RES-1) ? (sm[tid+1] - sm[tid]) : (sm[RES-1] - sm[RES-2]);
            dv[tid] = d;
        }
        __syncthreads();
        if (tid == 0) {
            float m = fabsf(dv[0]);
            for (int i = 1; i < RES; i++) m = fmaxf(m, fabsf(dv[i]));
            red = m;
        }
        __syncthreads();
        if (tid < RES) out[k*RES + tid] = dv[tid] / (red + 1e-8f);
    }
}

extern "C" void kernel_launch(void* const* d_in, const int* in_sizes, int n_in,
                              void* d_out, int out_size)
{
    const float* pts = (const float*)d_in[0];
    float* out = (float*)d_out;

    cudaFuncSetAttribute(mega_kernel, cudaFuncAttributeMaxDynamicSharedMemorySize, SMEMB);

    init_kernel<<<1, 64>>>();
    dist_kernel<<<NN/256, 256>>>(pts);
    adj_rowsum_kernel<<<NT*N, 128>>>();
    sq_kernel<<<1, 64>>>();

    dim3 gE(NN/256, NT);
    buildM_kernel<<<gE, 256>>>();

    // entire GEMM chain: one persistent kernel, work-stealing + grid barriers
    mega_kernel<<<NCTA, 256, SMEMB>>>();

    final_kernel<<<1, 128>>>(out);
}

// round 15
// speedup vs baseline: 1.1699x; 1.0906x over previous
#include <cuda_runtime.h>
#include <cuda_fp16.h>
#include <math.h>
#include <stdint.h>

#define N 768
#define NT 50
#define NN (N*N)
#define SIGMA 0.1f
#define RES 100
#define NL 5
#define KC 32
#define NCHUNK (N/KC)   // 24
#define NCTA 296        // 148 SMs x occ 2 - all co-resident (required for barriers/deps)
#define NSTAGES 7
#define MAXQ 11

// Taylor coefficients 1/k!
#define C0  1.0f
#define C1  1.0f
#define C2  0.5f
#define C3  (1.0f/6.0f)
#define C4  (1.0f/24.0f)
#define C5  (1.0f/120.0f)
#define C6  (1.0f/720.0f)
#define C7  (1.0f/5040.0f)
#define C8  (1.0f/40320.0f)
#define C9  (1.0f/362880.0f)
#define C10 (1.0f/3628800.0f)
#define C11 (1.0f/39916800.0f)
#define C12 (2.0876757e-9f)
#define C13 (1.6059044e-10f)
#define C14 (1.1470746e-11f)
#define C15 (7.6471637e-13f)

// epilogue write modes
#define WM_NEVER   0
#define WM_ALWAYS  1
// fused reduction kinds
#define RK_NONE  0
#define RK_TRACE 1
#define RK_FROB  2

// ---------------- global scratch ----------------
__device__ float g_dist[NN];
__device__ float g_r[NT*N];
__device__ float g_rmax[NT];
__device__ int   g_s[NT];
__device__ int   g_q[NT];
__device__ float g_scale[NT];
__device__ float g_maxdist;
__device__ float g_betti[NT];
__device__ unsigned g_ticket[NSTAGES];
__device__ unsigned g_bar[NSTAGES];
__device__ unsigned g_cnt[NT*12];      // per-(t,iter) completed-tile counters
// fp32 buffers: 0=M 1=M2 2=M3 3=M4 4/5 = ping-pong
// g_buf[5] doubles as the sigmoid cache between adj_rowsum and buildM.
__device__ float g_buf[6][(size_t)NT*NN];
// fp16 limb planes (2 per buffer); 16B-aligned for cp.async/uint2
__device__ __align__(16) __half g_limb[6][2][(size_t)NT*NN];

// stage table
struct StageDesc {
    int kind;      // 0 = gemm (global-barrier stage), 1 = elw_g3, 2 = squaring superstage
    int ai, bi, ci, addG;
    int fm, lm, rm, units, merged;   // rm: 0 none, 1 final-exp fused reduction
    float g0, g1, g2, g3;
};
__device__ const StageDesc g_stg[NSTAGES] = {
    {0, 0,0,1, 0, WM_ALWAYS, WM_ALWAYS, 0, 1050, 0, 0,0,0,0},        // M2
    {0, 1,0,2, 0, WM_ALWAYS, WM_NEVER,  0, 2100, 1, 0,0,0,0},        // M3 + M4 merged
    {1, 0,0,0, 0, 0, 0, 0,               1800, 0, 0,0,0,0},          // G3 elementwise
    {0, 3,4,5, 1, WM_NEVER, WM_ALWAYS,  0, 1050, 0, C8,C9,C10,C11},  // PS1
    {0, 3,5,4, 1, WM_NEVER, WM_ALWAYS,  0, 1050, 0, C4,C5,C6,C7},    // PS2
    {0, 3,4,5, 1, WM_NEVER, WM_ALWAYS,  1, 1050, 0, C0,C1,C2,C3},    // PS3 = exp(M)
    {2, 0,0,0, 0, 0, 0, 0,           MAXQ*1050, 0, 0,0,0,0},         // squaring superstage
};

// ---------------- helpers ----------------
__device__ __forceinline__ void atomicMaxF(float* addr, float v) {
    atomicMax((int*)addr, __float_as_int(v));   // non-negative floats
}
__device__ __forceinline__ uint32_t smem_u32(const void* p) {
    uint32_t a;
    asm("{ .reg .u64 t; cvta.to.shared.u64 t, %1; cvt.u32.u64 %0, t; }" : "=r"(a) : "l"(p));
    return a;
}
__device__ __forceinline__ void cp16(uint32_t s, const void* g) {
    asm volatile("cp.async.cg.shared.global [%0], [%1], 16;" :: "r"(s), "l"(g));
}
#define CP_COMMIT() asm volatile("cp.async.commit_group;" ::: "memory")
#define CP_WAIT(n)  asm volatile("cp.async.wait_group %0;" :: "n"(n) : "memory")

__device__ __forceinline__ void ldm_x4(uint32_t* r, uint32_t addr) {
    asm volatile("ldmatrix.sync.aligned.m8n8.x4.shared.b16 {%0,%1,%2,%3}, [%4];"
                 : "=r"(r[0]), "=r"(r[1]), "=r"(r[2]), "=r"(r[3]) : "r"(addr));
}
__device__ __forceinline__ void mma16816(float* d, const uint32_t* a, const uint32_t* b) {
    asm volatile(
        "mma.sync.aligned.m16n8k16.row.col.f32.f16.f16.f32 "
        "{%0,%1,%2,%3}, {%4,%5,%6,%7}, {%8,%9}, {%0,%1,%2,%3};"
        : "+f"(d[0]), "+f"(d[1]), "+f"(d[2]), "+f"(d[3])
        : "r"(a[0]), "r"(a[1]), "r"(a[2]), "r"(a[3]), "r"(b[0]), "r"(b[1]));
}

__device__ __forceinline__ uint32_t packh(__half lo, __half hi) {
    __half2 t = __halves2half2(lo, hi);
    return *reinterpret_cast<uint32_t*>(&t);
}
__device__ __forceinline__ void split2(float x, __half& h0, __half& h1) {
    h0 = __float2half_rn(x);
    h1 = __float2half_rn(x - __half2float(h0));
}
__device__ __forceinline__ void split2x4(float4 v, uint2& L0, uint2& L1) {
    __half a0,a1,b0,b1,c0,c1,d0,d1;
    split2(v.x, a0,a1); split2(v.y, b0,b1);
    split2(v.z, c0,c1); split2(v.w, d0,d1);
    L0 = make_uint2(packh(a0,b0), packh(c0,d0));
    L1 = make_uint2(packh(a1,b1), packh(c1,d1));
}

// ---------------- preamble kernels ----------------
__global__ void init_kernel() {
    int t = threadIdx.x;
    if (t < NT) { g_rmax[t] = 0.0f; g_betti[t] = 0.0f; }
    if (t < NSTAGES) { g_ticket[t] = 0u; g_bar[t] = 0u; }
    for (int i = t; i < NT*12; i += blockDim.x) g_cnt[i] = 0u;
    if (t == 0) g_maxdist = 0.0f;
}

__global__ void dist_kernel(const float* __restrict__ pts) {
    __shared__ float p[N*3];
    for (int i = threadIdx.x; i < N*3; i += blockDim.x) p[i] = pts[i];
    __syncthreads();
    int idx = blockIdx.x * blockDim.x + threadIdx.x;
    float d = 0.0f;
    if (idx < NN) {
        int i = idx / N, j = idx - i*N;
        float dx = p[i*3+0] - p[j*3+0];
        float dy = p[i*3+1] - p[j*3+1];
        float dz = p[i*3+2] - p[j*3+2];
        d = sqrtf(dx*dx + dy*dy + dz*dz);
        g_dist[idx] = d;
    }
    __shared__ float red[256];
    red[threadIdx.x] = d;
    __syncthreads();
    for (int off = 128; off > 0; off >>= 1) {
        if (threadIdx.x < off) red[threadIdx.x] = fmaxf(red[threadIdx.x], red[threadIdx.x+off]);
        __syncthreads();
    }
    if (threadIdx.x == 0) atomicMaxF(&g_maxdist, red[0]);
}

// sigmoid row computed ONCE, cached in g_buf[5]; off-diagonal row sum reduced.
__global__ void adj_rowsum_kernel() {
    int bid = blockIdx.x;           // t*N + i
    int t = bid / N, i = bid - t*N;
    float th = ((float)t / (float)(NT-1)) * g_maxdist;
    const float* drow = g_dist + (size_t)i*N;
    float* arow = g_buf[5] + (size_t)t*NN + (size_t)i*N;
    float s = 0.0f;
    for (int j = threadIdx.x; j < N; j += blockDim.x) {
        float e = expf((drow[j] - th) / SIGMA);
        float a = 1.0f / (1.0f + e);
        arow[j] = a;
        if (j != i) s += a;
    }
    __shared__ float red[128];
    red[threadIdx.x] = s;
    __syncthreads();
    for (int off = 64; off > 0; off >>= 1) {
        if (threadIdx.x < off) red[threadIdx.x] += red[threadIdx.x+off];
        __syncthreads();
    }
    if (threadIdx.x == 0) {
        g_r[bid] = red[0];
        atomicMaxF(&g_rmax[t], red[0]);
    }
}

// Gershgorin bound: lambda_max(L) <= 2*max_row_sum. Slack is load-bearing
// (round-8 post-mortem): keeps true ||M|| ~ theta/2 for the fp16-limb chain.
__global__ void sq_kernel() {
    int t = threadIdx.x;
    if (t < NT) {
        float x = 2.0f * g_rmax[t] / SIGMA;
        int s = 0;
        if (x > 4.0f) s = (int)ceilf(log2f(x * 0.25f));   // scale to ||M|| <= 4
        if (s < 0) s = 0;
        if (s > 12) s = 12;
        g_s[t] = s;
        g_q[t] = (s > 1) ? (s - 1) : 0;
        g_scale[t] = exp2f((float)(-s)) / SIGMA;
    }
}

// M = -L/(sigma*2^s) from the cached adjacency; also emit fp16 limbs of M
__global__ void buildM_kernel() {
    int t = blockIdx.y;
    int idx = blockIdx.x * blockDim.x + threadIdx.x;
    if (idx >= NN) return;
    int i = idx / N, j = idx - i*N;
    float sc = g_scale[t];
    size_t o = (size_t)t*NN + idx;
    float v = (i == j) ? (-g_r[t*N + i] * sc) : (g_buf[5][o] * sc);
    g_buf[0][o] = v;
    __half h0, h1;
    split2(v, h0, h1);
    g_limb[0][0][o] = h0; g_limb[0][1][o] = h1;
}

// ---------------- persistent mega-kernel ----------------
#define TILEB 10240          // 128*80
#define BUFB  (4*TILEB)      // 40960
#define SMEMB (2*BUFB)       // 81920
#define CPIT  132            // C_sm pitch (floats); multiple of 4 -> 16B rows

// One 128x128 output tile (lower-triangle index btr>=btc) of C = A*B^T (+G poly).
__device__ void gemm_tile(int ai, int bi, int ci, int addG,
                          float gc0, float gc1, float gc2, float gc3,
                          bool wF, bool wL, int rkind,
                          int t, int btr, int btc,
                          int tid, char* smem, uint32_t sb)
{
    int row0 = btr * 128, col0 = btc * 128;
    int wid = tid >> 5, lane = tid & 31;
    int wm = wid >> 2, wn = wid & 3;

    bool same = (ai == bi) && (btr == btc);
    const __half* pA[2] = { g_limb[ai][0] + (size_t)t*NN, g_limb[ai][1] + (size_t)t*NN };
    const __half* pB[2] = { g_limb[bi][0] + (size_t)t*NN, g_limb[bi][1] + (size_t)t*NN };
    float* C = g_buf[ci] + (size_t)t*NN;

    float acc[4][4][4];
    #pragma unroll
    for (int a = 0; a < 4; a++)
        #pragma unroll
        for (int b = 0; b < 4; b++)
            #pragma unroll
            for (int c = 0; c < 4; c++) acc[a][b][c] = 0.0f;

    uint32_t aLane = (uint32_t)((wm*64 + (lane & 15))*80 + ((lane >> 4)*16));
    uint32_t bLane = (uint32_t)((wn*32 + (lane & 7) + ((lane >> 4) << 3))*80 + (((lane >> 3) & 1)*16));
    const int nTiles = same ? 2 : 4;
    const int totCp = nTiles * 512;

    auto issue = [&](int c, int buf) {
        uint32_t bb = sb + buf*BUFB;
        int cK = c*KC;
        for (int idx = tid; idx < totCp; idx += 256) {
            int tile = idx >> 9;
            int rr2 = (idx & 511) >> 2, q2 = idx & 3;
            const __half* src = (tile < 2)
                ? pA[tile] + (size_t)(row0 + rr2)*N + cK + q2*8
                : pB[tile-2] + (size_t)(col0 + rr2)*N + cK + q2*8;
            cp16(bb + tile*TILEB + rr2*80 + q2*16, src);
        }
    };

    issue(0, 0); CP_COMMIT();

    for (int c = 0; c < NCHUNK; c++) {
        if (c + 1 < NCHUNK) { issue(c+1, (c+1)&1); CP_COMMIT(); CP_WAIT(1); }
        else CP_WAIT(0);
        __syncthreads();

        uint32_t bb  = sb + (c&1)*BUFB;
        uint32_t bbB = same ? bb : bb + 2*TILEB;
        #pragma unroll
        for (int ks = 0; ks < 2; ks++) {
            uint32_t af0[4][4], af1[4][4], bf0[2][4], bf1[2][4];
            {
                uint32_t base = bbB + bLane + ks*32;
                ldm_x4(bf0[0], base);            ldm_x4(bf0[1], base + 16*80);
                ldm_x4(bf1[0], base + TILEB);    ldm_x4(bf1[1], base + TILEB + 16*80);
            }
            {
                uint32_t base = bb + aLane + ks*32;
                #pragma unroll
                for (int mt = 0; mt < 4; mt++) {
                    ldm_x4(af0[mt], base + mt*16*80);
                    ldm_x4(af1[mt], base + TILEB + mt*16*80);
                }
            }
            // 3 limb products, product-first
            #pragma unroll
            for (int mt = 0; mt < 4; mt++)
                #pragma unroll
                for (int nt = 0; nt < 4; nt++)
                    mma16816(acc[mt][nt], af0[mt], &bf0[nt>>1][(nt&1)*2]);
            #pragma unroll
            for (int mt = 0; mt < 4; mt++)
                #pragma unroll
                for (int nt = 0; nt < 4; nt++)
                    mma16816(acc[mt][nt], af0[mt], &bf1[nt>>1][(nt&1)*2]);
            #pragma unroll
            for (int mt = 0; mt < 4; mt++)
                #pragma unroll
                for (int nt = 0; nt < 4; nt++)
                    mma16816(acc[mt][nt], af1[mt], &bf0[nt>>1][(nt&1)*2]);
        }
        __syncthreads();
    }

    // ---- epilogue via smem ----
    float* C_sm = (float*)smem;
    {
        int g = lane >> 2, j2 = (lane & 3) * 2;
        #pragma unroll
        for (int mt = 0; mt < 4; mt++)
            #pragma unroll
            for (int nt = 0; nt < 4; nt++) {
                int rr = wm*64 + mt*16 + g;
                int cc = wn*32 + nt*8 + j2;
                C_sm[rr*CPIT + cc]       = acc[mt][nt][0];
                C_sm[rr*CPIT + cc + 1]   = acc[mt][nt][1];
                C_sm[(rr+8)*CPIT + cc]   = acc[mt][nt][2];
                C_sm[(rr+8)*CPIT + cc+1] = acc[mt][nt][3];
            }
    }
    __syncthreads();

    const float* Mp  = g_buf[0] + (size_t)t*NN;
    const float* M2p = g_buf[1] + (size_t)t*NN;
    const float* M3p = g_buf[2] + (size_t)t*NN;
    __half* L0 = g_limb[ci][0] + (size_t)t*NN;
    __half* L1 = g_limb[ci][1] + (size_t)t*NN;

    float rsum = 0.0f;
    {   // phase A: lower tile, row-coalesced
        int rr = tid & 127, h = tid >> 7;
        size_t rowOff = (size_t)(row0 + rr)*N + col0;
        float w = (btr == btc) ? 1.0f : 2.0f;
        #pragma unroll
        for (int i = 0; i < 16; i++) {
            int ce = h*64 + i*4;
            float4 v = *(float4*)&C_sm[rr*CPIT + ce];
            if (addG) {
                float4 m1 = *(const float4*)(Mp  + rowOff + ce);
                float4 m2 = *(const float4*)(M2p + rowOff + ce);
                float4 m3 = *(const float4*)(M3p + rowOff + ce);
                v.x += gc1*m1.x + gc2*m2.x + gc3*m3.x;
                v.y += gc1*m1.y + gc2*m2.y + gc3*m3.y;
                v.z += gc1*m1.z + gc2*m2.z + gc3*m3.z;
                v.w += gc1*m1.w + gc2*m2.w + gc3*m3.w;
                if (btr == btc) {
                    int k = rr - ce;
                    if (k >= 0 && k < 4) (&v.x)[k] += gc0;
                }
                if (btr != btc) *(float4*)&C_sm[rr*CPIT + ce] = v;
            }
            if (wF) *(float4*)(C + rowOff + ce) = v;
            if (wL) {
                uint2 l0, l1;
                split2x4(v, l0, l1);
                *(uint2*)(L0 + rowOff + ce) = l0;
                *(uint2*)(L1 + rowOff + ce) = l1;
            }
            if (rkind == RK_FROB) {
                rsum += w * (v.x*v.x + v.y*v.y + v.z*v.z + v.w*v.w);
            } else if (rkind == RK_TRACE) {
                if (btr == btc) {
                    int k = rr - ce;
                    if (k >= 0 && k < 4) rsum += (&v.x)[k];
                }
            }
        }
    }
    if (btr != btc && (wF || wL)) {   // phase B: mirror
        __syncthreads();
        int u2 = tid >> 1, hh = tid & 1;
        size_t rowOff = (size_t)(col0 + u2)*N + row0;
        #pragma unroll
        for (int i = 0; i < 16; i++) {
            int x0 = hh*64 + i*4;
            float4 v = make_float4(C_sm[(x0  )*CPIT + u2], C_sm[(x0+1)*CPIT + u2],
                                   C_sm[(x0+2)*CPIT + u2], C_sm[(x0+3)*CPIT + u2]);
            if (wF) *(float4*)(C + rowOff + x0) = v;
            if (wL) {
                uint2 l0, l1;
                split2x4(v, l0, l1);
                *(uint2*)(L0 + rowOff + x0) = l0;
                *(uint2*)(L1 + rowOff + x0) = l1;
            }
        }
    }
    if (rkind) {
        __shared__ float redsm[256];
        redsm[tid] = rsum;
        __syncthreads();
        for (int off = 128; off > 0; off >>= 1) {
            if (tid < off) redsm[tid] += redsm[tid + off];
            __syncthreads();
        }
        if (tid == 0) atomicAdd(&g_betti[t], redsm[0]);
    }
    __syncthreads();
}

// G3 elementwise: buf4 limbs = C12*I + C13*M + C14*M2 + C15*M3 on a 128x128 tile
__device__ void elw_unit(int u, int tid)
{
    int t = u / 36, tile = u - t*36;
    int tr = tile / 6, tc = tile - tr*6;
    int rr = tid >> 1, hh = (tid & 1) * 64;
    size_t o = (size_t)t*NN + (size_t)(tr*128 + rr)*N + tc*128 + hh;
    const float* Mp  = g_buf[0];
    const float* M2p = g_buf[1];
    const float* M3p = g_buf[2];
    __half* L0 = g_limb[4][0];
    __half* L1 = g_limb[4][1];
    #pragma unroll
    for (int i = 0; i < 16; i++) {
        float4 m1 = *(const float4*)(Mp  + o + i*4);
        float4 m2 = *(const float4*)(M2p + o + i*4);
        float4 m3 = *(const float4*)(M3p + o + i*4);
        float4 v;
        v.x = C13*m1.x + C14*m2.x + C15*m3.x;
        v.y = C13*m1.y + C14*m2.y + C15*m3.y;
        v.z = C13*m1.z + C14*m2.z + C15*m3.z;
        v.w = C13*m1.w + C14*m2.w + C15*m3.w;
        if (tr == tc) {
            int k = rr - (hh + i*4);
            if (k >= 0 && k < 4) (&v.x)[k] += C12;
        }
        uint2 l0, l1;
        split2x4(v, l0, l1);
        *(uint2*)(L0 + o + i*4) = l0;
        *(uint2*)(L1 + o + i*4) = l1;
    }
}

__device__ __forceinline__ void decode_tri(int tileIdx, int& btr, int& btc) {
    int r = 0, rem = tileIdx;
    while (rem > r) { rem -= (r + 1); r++; }
    btr = r; btc = rem;
}

__global__ void __launch_bounds__(256, 2) mega_kernel()
{
    extern __shared__ char smem[];
    uint32_t sb = smem_u32(smem);
    int tid = threadIdx.x;
    __shared__ int s_unit;

    for (int s = 0; s < NSTAGES; s++) {
        StageDesc st = g_stg[s];
        for (;;) {
            __syncthreads();
            if (tid == 0) s_unit = (int)atomicAdd(&g_ticket[s], 1u);
            __syncthreads();
            int u = s_unit;
            if (u >= st.units) break;

            if (st.kind == 0) {
                int op = 0;
                if (st.merged) { op = u / 1050; u -= op * 1050; }
                int t = u / 21, tileIdx = u - t*21;
                int ai = st.ai, bi = st.bi, ci = st.ci;
                bool wF = (st.fm == WM_ALWAYS), wL = (st.lm == WM_ALWAYS);
                if (op == 1) { ai = 1; bi = 1; ci = 3; wF = false; wL = true; }
                int q = g_q[t];
                int rkind = RK_NONE;
                if (st.rm == 1 && q == 0) rkind = (g_s[t] == 0) ? RK_TRACE : RK_FROB;
                int btr, btc; decode_tri(tileIdx, btr, btc);
                gemm_tile(ai, bi, ci, st.addG, st.g0, st.g1, st.g2, st.g3,
                          wF, wL, rkind, t, btr, btc, tid, smem, sb);
            } else if (st.kind == 1) {
                elw_unit(u, tid);
            } else {
                // squaring superstage: unit = (iter, t, tile), iter-major tickets
                int iter = u / 1050;
                int rem = u - iter*1050;
                int t = rem / 21, tileIdx = rem - t*21;
                int q = g_q[t];
                if (iter >= q) continue;   // inactive (block-uniform)
                // dataflow dependency: previous squaring of this t fully written
                if (iter > 0) {
                    if (tid == 0) {
                        while (atomicAdd(&g_cnt[t*12 + (iter-1)], 0u) < 21u) __nanosleep(128);
                        __threadfence();   // acquire
                    }
                    __syncthreads();
                }
                int src = (iter & 1) ? 4 : 5;
                int dst = (iter & 1) ? 5 : 4;
                bool wL = (iter < q-1);
                int rkind = (iter == q-1) ? RK_FROB : RK_NONE;
                int btr, btc; decode_tri(tileIdx, btr, btc);
                gemm_tile(src, src, dst, 0, 0,0,0,0,
                          false, wL, rkind, t, btr, btc, tid, smem, sb);
                if (tid == 0) {
                    __threadfence();       // release tile writes
                    atomicAdd(&g_cnt[t*12 + iter], 1u);
                }
            }
        }
        // global barrier between stages 0..5; after the superstage it just drains
        if (tid == 0) {
            __threadfence();
            atomicAdd(&g_bar[s], 1u);
            while (*((volatile unsigned*)&g_bar[s]) < NCTA) __nanosleep(64);
            __threadfence();
        }
        __syncthreads();
    }
}

__global__ void final_kernel(float* __restrict__ out) {
    __shared__ float b[NT];
    __shared__ float bi[RES], sm[RES], dv[RES];
    __shared__ float red;
    int tid = threadIdx.x;
    if (tid < NT) b[tid] = g_betti[tid];
    __syncthreads();
    if (tid < RES) {
        float pos = (float)(NT-1) * (float)tid / (float)(RES-1);
        int i0 = (int)floorf(pos);
        if (i0 > NT-2) i0 = NT-2;
        if (i0 < 0) i0 = 0;
        float fr = pos - (float)i0;
        bi[tid] = b[i0]*(1.0f - fr) + b[i0+1]*fr;
    }
    __syncthreads();
    if (tid == 0) {
        float m = bi[0];
        for (int i = 1; i < RES; i++) m = fmaxf(m, bi[i]);
        red = m;
    }
    __syncthreads();
    if (tid < RES) out[tid] = bi[tid] / (red + 1e-8f);

    for (int k = 1; k < NL; k++) {
        int ks = 2*k + 1;
        int pad = ks / 2;
        __syncthreads();
        if (tid < RES) {
            float s = 0.0f;
            for (int u = -pad; u <= pad; u++) {
                int j = tid + u;
                j = max(0, min(RES-1, j));
                s += bi[j];
            }
            sm[tid] = s / (float)ks;
        }
        __syncthreads();
        if (tid < RES) {
            float d = (tid < RES-1) ? (sm[tid+1] - sm[tid]) : (sm[RES-1] - sm[RES-2]);
            dv[tid] = d;
        }
        __syncthreads();
        if (tid == 0) {
            float m = fabsf(dv[0]);
            for (int i = 1; i < RES; i++) m = fmaxf(m, fabsf(dv[i]));
            red = m;
        }
        __syncthreads();
        if (tid < RES) out[k*RES + tid] = dv[tid] / (red + 1e-8f);
    }
}

extern "C" void kernel_launch(void* const* d_in, const int* in_sizes, int n_in,
                              void* d_out, int out_size)
{
    const float* pts = (const float*)d_in[0];
    float* out = (float*)d_out;

    cudaFuncSetAttribute(mega_kernel, cudaFuncAttributeMaxDynamicSharedMemorySize, SMEMB);

    init_kernel<<<1, 256>>>();
    dist_kernel<<<NN/256, 256>>>(pts);
    adj_rowsum_kernel<<<NT*N, 128>>>();
    sq_kernel<<<1, 64>>>();

    dim3 gE(NN/256, NT);
    buildM_kernel<<<gE, 256>>>();

    // entire GEMM chain: one persistent kernel; squaring chain runs on
    // per-(t,iter) dataflow dependencies instead of global barriers
    mega_kernel<<<NCTA, 256, SMEMB>>>();

    final_kernel<<<1, 128>>>(out);
}